// round 1
// baseline (speedup 1.0000x reference)
#include <cuda_runtime.h>

#define BN 512     // batch (i and j)
#define HH 512     // hidden
#define DX 128     // dim_x = dim_y

// Scratch (device globals: no allocation allowed in kernel_launch)
__device__ float hxT_g[HH * BN];     // [h][i]  = x@W1x + b1   (b1 folded)
__device__ float nhyT_g[HH * BN];    // [h][j]  = -(y@W1y)
__device__ float part_g[4 * BN * BN];// per-h-chunk partial scores

// ---------------------------------------------------------------------------
// prep: compute hxT (b1 folded) and nhyT (negated), transposed to [h][row].
// grid (8 row-tiles, 8 h-tiles, 2 {x,y}), 256 threads, 64x64 tile, 4x4/thread.
// ---------------------------------------------------------------------------
__global__ void __launch_bounds__(256) prep_kernel(
    const float* __restrict__ x, const float* __restrict__ y,
    const float* __restrict__ W1, const float* __restrict__ b1)
{
    __shared__ float Ws[64][64];   // [k][h]
    __shared__ float As[64][68];   // [k][row], padded, 16B-aligned rows

    const int r0   = blockIdx.x * 64;
    const int h0   = blockIdx.y * 64;
    const bool isY = (blockIdx.z != 0);
    const float* __restrict__ in = isY ? y : x;
    const int wrow0 = isY ? DX : 0;

    const int tid = threadIdx.x;
    const int th  = tid >> 4;   // 0..15 : h frag = th*4
    const int tr  = tid & 15;   // 0..15 : row frag = tr*4

    float acc[4][4] = {};

    for (int kc = 0; kc < 2; kc++) {
        __syncthreads();
        // stage W1 tile [64k x 64h]
        for (int t = tid; t < 1024; t += 256) {
            int k = t >> 4, q = t & 15;
            *(float4*)&Ws[k][q * 4] =
                *(const float4*)(W1 + (wrow0 + kc * 64 + k) * HH + h0 + q * 4);
        }
        // stage input tile transposed: As[k][r]
        for (int t = tid; t < 1024; t += 256) {
            int r = t & 63, kq = t >> 6;   // kq 0..15
            float4 v = *(const float4*)(in + (r0 + r) * DX + kc * 64 + kq * 4);
            As[kq * 4 + 0][r] = v.x;
            As[kq * 4 + 1][r] = v.y;
            As[kq * 4 + 2][r] = v.z;
            As[kq * 4 + 3][r] = v.w;
        }
        __syncthreads();

        #pragma unroll 8
        for (int k = 0; k < 64; k++) {
            float4 wf = *(const float4*)&Ws[k][th * 4];
            float4 af = *(const float4*)&As[k][tr * 4];
            float wa[4] = {wf.x, wf.y, wf.z, wf.w};
            float aa[4] = {af.x, af.y, af.z, af.w};
            #pragma unroll
            for (int a = 0; a < 4; a++)
                #pragma unroll
                for (int b = 0; b < 4; b++)
                    acc[a][b] = fmaf(wa[a], aa[b], acc[a][b]);
        }
    }

    float* outg = isY ? nhyT_g : hxT_g;
    #pragma unroll
    for (int a = 0; a < 4; a++) {
        int h = h0 + th * 4 + a;
        float4 o;
        if (isY) {
            o.x = -acc[a][0]; o.y = -acc[a][1]; o.z = -acc[a][2]; o.w = -acc[a][3];
        } else {
            float bb = b1[h];
            o.x = acc[a][0] + bb; o.y = acc[a][1] + bb;
            o.z = acc[a][2] + bb; o.w = acc[a][3] + bb;
        }
        *(float4*)(outg + h * BN + r0 + tr * 4) = o;
    }
}

// ---------------------------------------------------------------------------
// main: partial[z][i,j] = sum_{h in chunk z} max(hxT[h][i], nhyT[h][j])*w2[h]
//                         + sum_{h in chunk z} hy[j,h]*w2[h]       (gy part)
// grid (8 j-tiles, 4 i-tiles, 4 h-chunks) = 128 blocks, 256 threads.
// block tile: 128 i x 64 j x 128 h. thread tile: 8x4.
// ---------------------------------------------------------------------------
__global__ void __launch_bounds__(256) main_kernel(const float* __restrict__ W2)
{
    __shared__ float Axs[32][128];  // [h][i]
    __shared__ float Bys[32][64];   // [h][j] (negated hy)
    __shared__ float w2s[32];
    __shared__ float gybuf[4][64];

    const int j0 = blockIdx.x * 64;
    const int i0 = blockIdx.y * 128;
    const int hb = blockIdx.z * 128;

    const int tid = threadIdx.x;
    const int ti  = tid >> 4;    // 0..15 : i frag = ti*8
    const int tj  = tid & 15;    // 0..15 : j frag = tj*4
    const int gj  = tid & 63;    // gy: which j
    const int gq  = tid >> 6;    // gy: which h strip (0..3)

    float acc[8][4] = {};
    float gyp = 0.f;

    for (int c = 0; c < 4; c++) {
        const int h0 = hb + c * 32;
        __syncthreads();
        // stage hx chunk [32h x 128i]
        for (int t = tid; t < 1024; t += 256) {
            int h = t >> 5, q = t & 31;
            *(float4*)&Axs[h][q * 4] =
                *(const float4*)(hxT_g + (h0 + h) * BN + i0 + q * 4);
        }
        // stage -hy chunk [32h x 64j]
        for (int t = tid; t < 512; t += 256) {
            int h = t >> 4, q = t & 15;
            *(float4*)&Bys[h][q * 4] =
                *(const float4*)(nhyT_g + (h0 + h) * BN + j0 + q * 4);
        }
        if (tid < 32) w2s[tid] = W2[h0 + tid];
        __syncthreads();

        #pragma unroll 4
        for (int h = 0; h < 32; h++) {
            float4 a0 = *(const float4*)&Axs[h][ti * 8];
            float4 a1 = *(const float4*)&Axs[h][ti * 8 + 4];
            float4 bv = *(const float4*)&Bys[h][tj * 4];
            float w   = w2s[h];
            float av[8] = {a0.x, a0.y, a0.z, a0.w, a1.x, a1.y, a1.z, a1.w};
            float bb[4] = {bv.x, bv.y, bv.z, bv.w};
            #pragma unroll
            for (int r = 0; r < 8; r++)
                #pragma unroll
                for (int cc = 0; cc < 4; cc++)
                    acc[r][cc] = fmaf(fmaxf(av[r], bb[cc]), w, acc[r][cc]);
        }

        // gy partial for this chunk: thread (gq, gj) covers h = gq*8 .. gq*8+7
        #pragma unroll
        for (int hh = 0; hh < 8; hh++) {
            int h = gq * 8 + hh;
            gyp = fmaf(Bys[h][gj], w2s[h], gyp);   // accumulates -(hy*w2)
        }
    }

    __syncthreads();
    gybuf[gq][gj] = gyp;
    __syncthreads();

    float gyv[4];
    #pragma unroll
    for (int cc = 0; cc < 4; cc++) {
        int j = tj * 4 + cc;
        gyv[cc] = -(gybuf[0][j] + gybuf[1][j] + gybuf[2][j] + gybuf[3][j]);
    }

    float* p = part_g + blockIdx.z * (BN * BN);
    #pragma unroll
    for (int r = 0; r < 8; r++) {
        float4 o;
        o.x = acc[r][0] + gyv[0];
        o.y = acc[r][1] + gyv[1];
        o.z = acc[r][2] + gyv[2];
        o.w = acc[r][3] + gyv[3];
        *(float4*)(p + (i0 + ti * 8 + r) * BN + j0 + tj * 4) = o;
    }
}

// ---------------------------------------------------------------------------
// reduce: out = part0 + part1 + part2 + part3 + b2
// ---------------------------------------------------------------------------
__global__ void __launch_bounds__(256) reduce_kernel(
    const float* __restrict__ b2, float* __restrict__ out)
{
    int idx = blockIdx.x * 256 + threadIdx.x;        // float4 index, 65536 total
    const float4* p = (const float4*)part_g;
    float4 a = p[idx];
    float4 b = p[idx + 65536];
    float4 c = p[idx + 2 * 65536];
    float4 d = p[idx + 3 * 65536];
    float bias = b2[0];
    float4 o;
    o.x = a.x + b.x + c.x + d.x + bias;
    o.y = a.y + b.y + c.y + d.y + bias;
    o.z = a.z + b.z + c.z + d.z + bias;
    o.w = a.w + b.w + c.w + d.w + bias;
    ((float4*)out)[idx] = o;
}

// ---------------------------------------------------------------------------
extern "C" void kernel_launch(void* const* d_in, const int* in_sizes, int n_in,
                              void* d_out, int out_size)
{
    const float* x  = (const float*)d_in[0];
    const float* y  = (const float*)d_in[1];
    const float* W1 = (const float*)d_in[2];
    const float* b1 = (const float*)d_in[3];
    const float* W2 = (const float*)d_in[4];
    const float* b2 = (const float*)d_in[5];
    float* out = (float*)d_out;

    prep_kernel<<<dim3(8, 8, 2), 256>>>(x, y, W1, b1);
    main_kernel<<<dim3(8, 4, 4), 256>>>(W2);
    reduce_kernel<<<256, 256>>>(b2, out);
}

// round 2
// speedup vs baseline: 1.1199x; 1.1199x over previous
#include <cuda_runtime.h>
#include <cstdint>

#define BN 512     // batch (i and j)
#define HH 512     // hidden
#define DX 128     // dim_x = dim_y

// Scratch (device globals: no allocation allowed in kernel_launch)
__device__ __align__(16) float hxT_g[HH * BN];      // [h][i]  = x@W1x + b1
__device__ __align__(16) float nhyT_g[HH * BN];     // [h][j]  = -(y@W1y)
__device__ __align__(16) float part_g[8 * BN * BN]; // per-h-chunk partials

// Packed fp32x2 helpers (Blackwell)
#define PACK2(out, lo, hi) \
    asm("mov.b64 %0, {%1, %2};" : "=l"(out) : "f"(lo), "f"(hi))
#define UNPACK2(lo, hi, in) \
    asm("mov.b64 {%0, %1}, %2;" : "=f"(lo), "=f"(hi) : "l"(in))
#define FMA2(acc, a, b) \
    asm("fma.rn.f32x2 %0, %1, %2, %0;" : "+l"(acc) : "l"(a), "l"(b))

// ---------------------------------------------------------------------------
// prep: hxT (b1 folded) and nhyT (negated), transposed to [h][row].
// grid (8 r-tiles, 8 h-tiles, 2 {x,y}), 512 threads.
// tile 64r x 64h, thread tile 4r x 2h, FFMA2 inner loop.
// ---------------------------------------------------------------------------
__global__ void __launch_bounds__(512) prep_kernel(
    const float* __restrict__ x, const float* __restrict__ y,
    const float* __restrict__ W1, const float* __restrict__ b1)
{
    __shared__ float As[64][64];   // [k][r]
    __shared__ float Ws[64][64];   // [k][h]

    const int r0   = blockIdx.x * 64;
    const int h0   = blockIdx.y * 64;
    const bool isY = (blockIdx.z != 0);
    const float* __restrict__ in = isY ? y : x;
    const int wrow0 = isY ? DX : 0;

    const int tid = threadIdx.x;
    const int tr  = tid & 15;    // r frag = tr*4
    const int th  = tid >> 4;    // 0..31 : h frag = th*2

    uint64_t acc0a = 0, acc0b = 0, acc1a = 0, acc1b = 0; // packed (0.f,0.f)

    for (int kc = 0; kc < 2; kc++) {
        __syncthreads();
        // stage input tile transposed As[k][r]: lanes consecutive in r so the
        // scalar STS are conflict-free; gmem reads are 16B x 512B-stride.
        for (int t = tid; t < 1024; t += 512) {
            int r = t & 63, q = t >> 6;    // q 0..15
            float4 v = *(const float4*)(in + (r0 + r) * DX + kc * 64 + q * 4);
            As[q * 4 + 0][r] = v.x;
            As[q * 4 + 1][r] = v.y;
            As[q * 4 + 2][r] = v.z;
            As[q * 4 + 3][r] = v.w;
        }
        // stage W1 tile [64k x 64h]
        for (int t = tid; t < 1024; t += 512) {
            int k = t >> 4, q = t & 15;
            *(float4*)&Ws[k][q * 4] =
                *(const float4*)(W1 + (wrow0 + kc * 64 + k) * HH + h0 + q * 4);
        }
        __syncthreads();

        #pragma unroll 8
        for (int k = 0; k < 64; k++) {
            float4 av = *(const float4*)&As[k][tr * 4];
            float2 wv = *(const float2*)&Ws[k][th * 2];
            uint64_t a01, a23, w0d, w1d;
            PACK2(a01, av.x, av.y);
            PACK2(a23, av.z, av.w);
            PACK2(w0d, wv.x, wv.x);
            PACK2(w1d, wv.y, wv.y);
            FMA2(acc0a, a01, w0d);
            FMA2(acc0b, a23, w0d);
            FMA2(acc1a, a01, w1d);
            FMA2(acc1b, a23, w1d);
        }
    }

    float v0, v1, v2, v3;
    float* outg = isY ? nhyT_g : hxT_g;
    const int hA = h0 + th * 2;

    // hh = 0
    UNPACK2(v0, v1, acc0a);
    UNPACK2(v2, v3, acc0b);
    {
        float4 o;
        if (isY) { o.x = -v0; o.y = -v1; o.z = -v2; o.w = -v3; }
        else { float bb = b1[hA]; o.x = v0 + bb; o.y = v1 + bb; o.z = v2 + bb; o.w = v3 + bb; }
        *(float4*)(outg + hA * BN + r0 + tr * 4) = o;
    }
    // hh = 1
    UNPACK2(v0, v1, acc1a);
    UNPACK2(v2, v3, acc1b);
    {
        float4 o;
        if (isY) { o.x = -v0; o.y = -v1; o.z = -v2; o.w = -v3; }
        else { float bb = b1[hA + 1]; o.x = v0 + bb; o.y = v1 + bb; o.z = v2 + bb; o.w = v3 + bb; }
        *(float4*)(outg + (hA + 1) * BN + r0 + tr * 4) = o;
    }
}

// ---------------------------------------------------------------------------
// main: partial[z][i,j] = sum_{h in chunk z} max(hx[i,h], -hy[j,h])*w2[h]
//                         + sum_{h in chunk z} hy[j,h]*w2[h]        (gy part)
// grid (4 j-tiles, 4 i-tiles, 8 h-chunks) = 128 blocks, 512 threads.
// block tile 128i x 128j x 64h; thread tile 4i x 8j (j split {lo,hi+64}).
// ---------------------------------------------------------------------------
__global__ void __launch_bounds__(512) main_kernel(const float* __restrict__ W2)
{
    __shared__ float Axs[32][128];   // [h][i]
    __shared__ float Bys[32][128];   // [h][j] (negated hy)
    __shared__ float w2s[32];
    __shared__ float gybuf[4][128];

    const int j0 = blockIdx.x * 128;
    const int i0 = blockIdx.y * 128;
    const int hb = blockIdx.z * 64;

    const int tid = threadIdx.x;
    const int ti  = tid >> 4;    // 0..31 : i frag = ti*4
    const int tj  = tid & 15;    // j frags = tj*4 and 64 + tj*4
    const int gq  = tid >> 7;    // 0..3 gy strip
    const int gj  = tid & 127;   // gy j index

    float acc[4][8] = {};
    float gyp = 0.f;

    for (int s = 0; s < 2; s++) {
        const int h0 = hb + s * 32;
        __syncthreads();
        for (int t = tid; t < 1024; t += 512) {
            int h = t >> 5, q = t & 31;
            *(float4*)&Axs[h][q * 4] =
                *(const float4*)(hxT_g + (h0 + h) * BN + i0 + q * 4);
        }
        for (int t = tid; t < 1024; t += 512) {
            int h = t >> 5, q = t & 31;
            *(float4*)&Bys[h][q * 4] =
                *(const float4*)(nhyT_g + (h0 + h) * BN + j0 + q * 4);
        }
        if (tid < 32) w2s[tid] = W2[h0 + tid];
        __syncthreads();

        for (int hq = 0; hq < 8; hq++) {
            float4 wq = *(const float4*)&w2s[hq * 4];
            float wa[4] = {wq.x, wq.y, wq.z, wq.w};
            #pragma unroll
            for (int u = 0; u < 4; u++) {
                const int h = hq * 4 + u;
                float4 a  = *(const float4*)&Axs[h][ti * 4];
                float4 b0 = *(const float4*)&Bys[h][tj * 4];
                float4 b1v= *(const float4*)&Bys[h][64 + tj * 4];
                const float w = wa[u];
                float av[4] = {a.x, a.y, a.z, a.w};
                float bv[8] = {b0.x, b0.y, b0.z, b0.w, b1v.x, b1v.y, b1v.z, b1v.w};
                #pragma unroll
                for (int r = 0; r < 4; r++)
                    #pragma unroll
                    for (int c = 0; c < 8; c++)
                        acc[r][c] = fmaf(fmaxf(av[r], bv[c]), w, acc[r][c]);
            }
        }

        // gy partial: strip gq covers h = gq*8 .. gq*8+7 of this 32-h stage
        #pragma unroll
        for (int hh = 0; hh < 8; hh++) {
            int h = gq * 8 + hh;
            gyp = fmaf(Bys[h][gj], w2s[h], gyp);   // accumulates -(hy*w2)
        }
    }

    __syncthreads();
    gybuf[gq][gj] = gyp;
    __syncthreads();

    float gyv[8];
    #pragma unroll
    for (int c = 0; c < 8; c++) {
        int jl = (c < 4) ? (tj * 4 + c) : (64 + tj * 4 + (c - 4));
        gyv[c] = -(gybuf[0][jl] + gybuf[1][jl] + gybuf[2][jl] + gybuf[3][jl]);
    }

    float* p = part_g + blockIdx.z * (BN * BN);
    #pragma unroll
    for (int r = 0; r < 4; r++) {
        float4 o0, o1;
        o0.x = acc[r][0] + gyv[0];
        o0.y = acc[r][1] + gyv[1];
        o0.z = acc[r][2] + gyv[2];
        o0.w = acc[r][3] + gyv[3];
        o1.x = acc[r][4] + gyv[4];
        o1.y = acc[r][5] + gyv[5];
        o1.z = acc[r][6] + gyv[6];
        o1.w = acc[r][7] + gyv[7];
        const int row = i0 + ti * 4 + r;
        *(float4*)(p + row * BN + j0 + tj * 4) = o0;
        *(float4*)(p + row * BN + j0 + 64 + tj * 4) = o1;
    }
}

// ---------------------------------------------------------------------------
// reduce: out = sum of 8 partials + b2
// ---------------------------------------------------------------------------
__global__ void __launch_bounds__(256) reduce_kernel(
    const float* __restrict__ b2, float* __restrict__ out)
{
    int idx = blockIdx.x * 256 + threadIdx.x;     // float4 index, 65536 total
    const float4* p = (const float4*)part_g;
    float4 s = p[idx];
    #pragma unroll
    for (int k = 1; k < 8; k++) {
        float4 v = p[idx + k * 65536];
        s.x += v.x; s.y += v.y; s.z += v.z; s.w += v.w;
    }
    float bb = b2[0];
    s.x += bb; s.y += bb; s.z += bb; s.w += bb;
    ((float4*)out)[idx] = s;
}

// ---------------------------------------------------------------------------
extern "C" void kernel_launch(void* const* d_in, const int* in_sizes, int n_in,
                              void* d_out, int out_size)
{
    const float* x  = (const float*)d_in[0];
    const float* y  = (const float*)d_in[1];
    const float* W1 = (const float*)d_in[2];
    const float* b1 = (const float*)d_in[3];
    const float* W2 = (const float*)d_in[4];
    const float* b2 = (const float*)d_in[5];
    float* out = (float*)d_out;

    prep_kernel<<<dim3(8, 8, 2), 512>>>(x, y, W1, b1);
    main_kernel<<<dim3(4, 4, 8), 512>>>(W2);
    reduce_kernel<<<256, 256>>>(b2, out);
}